// round 16
// baseline (speedup 1.0000x reference)
#include <cuda_runtime.h>
#include <math.h>

// x is (B, F) row-major fp32
#define B_ROWS 32768
#define F_COLS 1024
#define F4     256                     // float4 per row
#define NBLK   512                     // contiguous 64-row slices, 4 CTAs/SM
#define ROWS_PER_CTA 64
#define STASH_ROWS 13                  // rows 0..12 in dynamic SMEM (53.2 KB)
#define REG_ROWS 3                     // rows 13..15 in registers
#define GRP0_ROW 16                    // global groups: rows 16..63 (12 x 4)
#define NGRP 12
#define STAT_CTAS 32                   // coalesced stats workers
#define SMEM_DYN (STASH_ROWS * 4096 + 2048)   // stash + sh_s/sh_q = 55296 B
#define EPS 1e-5f

// Scratch (allocations forbidden)
__device__ float g_psum[NBLK * F_COLS];   // (2 MB)  [slot][col]
__device__ float g_psqr[NBLK * F_COLS];   // (2 MB)
__device__ float g_mean[F_COLS];
__device__ float g_rstd[F_COLS];

// Sync state
__device__ unsigned g_count = 0;
__device__ volatile unsigned g_gen = 0;
__device__ unsigned g_done = 0;

__device__ __forceinline__ void grid_barrier(unsigned nblocks) {
    __syncthreads();
    if (threadIdx.x == 0) {
        unsigned gen = g_gen;
        __threadfence();
        unsigned arrived = atomicAdd(&g_count, 1u) + 1u;
        if (arrived == nblocks) {
            atomicExch(&g_count, 0u);
            __threadfence();
            g_gen = gen + 1u;
        } else {
            while (g_gen == gen) { __nanosleep(64); }
        }
        __threadfence();
    }
    __syncthreads();
}

// Coherent L2 load for same-launch data (never __ldg: hoistable past barrier)
__device__ __forceinline__ float4 ldcg4(const float4* p) {
    float4 v;
    asm volatile("ld.global.cg.v4.f32 {%0,%1,%2,%3}, [%4];"
                 : "=f"(v.x), "=f"(v.y), "=f"(v.z), "=f"(v.w) : "l"(p));
    return v;
}

// ---------------------------------------------------------------------------
// R15 base + extended stash: rows 0..12 in dynamic SMEM, rows 13..15 held in
// REGISTERS across the barrier (LTS-free), rows 16..63 re-read from global
// (backward pipelined; tail is L1/L2-hot). Phase 2a: 32 worker CTAs with
// coalesced 128B partial reads. One grid barrier + done-counter.
// ---------------------------------------------------------------------------
__global__ __launch_bounds__(256, 4) void msf_fused(const float* __restrict__ x,
                                                    const float* __restrict__ S_in,
                                                    float* __restrict__ out) {
    extern __shared__ char dyn[];
    float4 (*stash)[256] = reinterpret_cast<float4 (*)[256]>(dyn);
    float* sh_s = reinterpret_cast<float*>(dyn + STASH_ROWS * 4096);
    float* sh_q = sh_s + 256;

    const int bid = blockIdx.x;
    const int t = threadIdx.x;                    // column group 0..255
    const float4* __restrict__ x4 = reinterpret_cast<const float4*>(x);
    float4* __restrict__ o4 = reinterpret_cast<float4*>(out);
    const size_t sbase = (size_t)bid * ROWS_PER_CTA * F4 + t;

    if (bid == 0 && t == 0) g_done = 0;           // increments are post-barrier

    float4 keep0, keep1, keep2;                   // rows 13,14,15 live across barrier

    // ---------------- Phase 1: slice partials (+ stashes) ------------------
    {
        float4 s = make_float4(0.f, 0.f, 0.f, 0.f);
        float4 q = make_float4(0.f, 0.f, 0.f, 0.f);

#pragma unroll
        for (int g = 0; g < ROWS_PER_CTA / 8; ++g) {
            float4 v[8];
#pragma unroll
            for (int j = 0; j < 8; ++j)
                v[j] = __ldg(&x4[sbase + (size_t)(g * 8 + j) * F4]);
#pragma unroll
            for (int j = 0; j < 8; ++j) {          // compile-time selection
                const int row = g * 8 + j;
                if (row < STASH_ROWS) stash[row][t] = v[j];
            }
            if (g == 1) { keep0 = v[5]; keep1 = v[6]; keep2 = v[7]; }  // rows 13..15
#pragma unroll
            for (int j = 0; j < 8; ++j) {
                s.x += v[j].x; s.y += v[j].y; s.z += v[j].z; s.w += v[j].w;
                q.x = fmaf(v[j].x, v[j].x, q.x);
                q.y = fmaf(v[j].y, v[j].y, q.y);
                q.z = fmaf(v[j].z, v[j].z, q.z);
                q.w = fmaf(v[j].w, v[j].w, q.w);
            }
        }
        __stcs(&reinterpret_cast<float4*>(g_psum)[bid * F4 + t], s);
        __stcs(&reinterpret_cast<float4*>(g_psqr)[bid * F4 + t], q);
    }

    grid_barrier(NBLK);

    // ---------------- Phase 2a: coalesced stats (32 worker CTAs) -----------
    if (bid < STAT_CTAS) {
        const int c = t & 31;                 // lane -> consecutive columns
        const int g = t >> 5;                 // slot group 0..7 (64 slots each)
        const int col = bid * 32 + c;

        float s = 0.f, q = 0.f;
#pragma unroll 2
        for (int kb = 0; kb < 64; kb += 8) {
            float vs[8], vq[8];
#pragma unroll
            for (int j = 0; j < 8; ++j) {
                const size_t k = (size_t)(g * 64 + kb + j);
                vs[j] = __ldcg(&g_psum[k * F_COLS + col]);
                vq[j] = __ldcg(&g_psqr[k * F_COLS + col]);
            }
#pragma unroll
            for (int j = 0; j < 8; ++j) { s += vs[j]; q += vq[j]; }
        }
        sh_s[t] = s; sh_q[t] = q;
        __syncthreads();
#pragma unroll
        for (int w = 128; w >= 32; w >>= 1) {     // combine the 8 slot-groups
            if (t < w) { sh_s[t] += sh_s[t + w]; sh_q[t] += sh_q[t + w]; }
            __syncthreads();
        }
        if (t < 32) {
            const float n = (float)B_ROWS;
            float mean = sh_s[t] / n;
            float m2 = sh_q[t] - n * mean * mean + S_in[col];
            g_mean[col] = mean;
            g_rstd[col] = 1.0f / (sqrtf(m2 / (n - 1.0f)) + EPS);
        }
        __syncthreads();
        if (t == 0) {
            __threadfence();
            atomicAdd(&g_done, 1u);               // this CTA's 32 cols published
        }
    }

    // ---------------- Phase 2b: normalize ----------------------------------
    {
        float4 a[4], b[4];

        // group i covers rows GRP0_ROW+4i .. +3, i = 0..11 (backward walk)
#define LOADG(buf, i)                                                          \
        {                                                                      \
            const size_t hb = sbase + (size_t)(GRP0_ROW + (i) * 4) * F4;       \
            _Pragma("unroll")                                                  \
            for (int j = 0; j < 4; ++j)                                        \
                buf[j] = __ldcs(&x4[hb + (size_t)j * F4]);                     \
        }
#define STOREG(buf, i)                                                         \
        {                                                                      \
            const size_t hb = sbase + (size_t)(GRP0_ROW + (i) * 4) * F4;       \
            _Pragma("unroll")                                                  \
            for (int j = 0; j < 4; ++j) {                                      \
                float4 o;                                                      \
                o.x = (buf[j].x - m.x) * r.x;                                  \
                o.y = (buf[j].y - m.y) * r.y;                                  \
                o.z = (buf[j].z - m.z) * r.z;                                  \
                o.w = (buf[j].w - m.w) * r.w;                                  \
                __stcs(&o4[hb + (size_t)j * F4], o);                           \
            }                                                                  \
        }

        // Prefetch (independent of stats) -> hides done-counter wait
        LOADG(a, NGRP - 1)                         // rows 60..63 (L1-hot)
        LOADG(b, NGRP - 2)                         // rows 56..59

        if (t == 0) {
            while (__ldcg(&g_done) < (unsigned)STAT_CTAS) { __nanosleep(32); }
        }
        __syncthreads();
        __threadfence();

        const float4 m = ldcg4(&reinterpret_cast<const float4*>(g_mean)[t]);
        const float4 r = ldcg4(&reinterpret_cast<const float4*>(g_rstd)[t]);

        // register-stashed rows 13..15 first (frees 12 regs for the rotation)
        {
            float4 o;
            o.x = (keep0.x - m.x) * r.x; o.y = (keep0.y - m.y) * r.y;
            o.z = (keep0.z - m.z) * r.z; o.w = (keep0.w - m.w) * r.w;
            __stcs(&o4[sbase + (size_t)13 * F4], o);
            o.x = (keep1.x - m.x) * r.x; o.y = (keep1.y - m.y) * r.y;
            o.z = (keep1.z - m.z) * r.z; o.w = (keep1.w - m.w) * r.w;
            __stcs(&o4[sbase + (size_t)14 * F4], o);
            o.x = (keep2.x - m.x) * r.x; o.y = (keep2.y - m.y) * r.y;
            o.z = (keep2.z - m.z) * r.z; o.w = (keep2.w - m.w) * r.w;
            __stcs(&o4[sbase + (size_t)15 * F4], o);
        }

        // 12 groups backward, 2-buffer rotation
#pragma unroll
        for (int k = 0; k < NGRP; ++k) {
            const int i = NGRP - 1 - k;            // 11..0
            if ((k & 1) == 0) {
                STOREG(a, i)
                if (i >= 2) LOADG(a, i - 2)
            } else {
                STOREG(b, i)
                if (i >= 2) LOADG(b, i - 2)
            }
        }
#undef LOADG
#undef STOREG

        // rows 12..0 from the SMEM stash (zero LTS read traffic)
#pragma unroll
        for (int row = STASH_ROWS - 1; row >= 0; --row) {
            float4 v = stash[row][t];
            float4 o;
            o.x = (v.x - m.x) * r.x;
            o.y = (v.y - m.y) * r.y;
            o.z = (v.z - m.z) * r.z;
            o.w = (v.w - m.w) * r.w;
            __stcs(&o4[sbase + (size_t)row * F4], o);
        }
    }
}

extern "C" void kernel_launch(void* const* d_in, const int* in_sizes, int n_in,
                              void* d_out, int out_size) {
    const float* x    = (const float*)d_in[0];   // (32768, 1024) fp32
    // d_in[1] = running-mean buffer M: overwritten by first Welford sample -> unused
    const float* S_in = (const float*)d_in[2];   // (1024,) running M2, added into var
    float* out = (float*)d_out;

    cudaFuncSetAttribute(msf_fused, cudaFuncAttributeMaxDynamicSharedMemorySize,
                         SMEM_DYN);
    msf_fused<<<NBLK, 256, SMEM_DYN>>>(x, S_in, out);
}